// round 1
// baseline (speedup 1.0000x reference)
#include <cuda_runtime.h>
#include <cuda_bf16.h>
#include <cstdint>

// GeoEncoder: tri-plane + tri-line sampling with 48->32 projection.
// Strategy:
//   1) transpose planes [48][512][512] -> [512][512][48] into __device__ scratch
//      (192B contiguous per texel -> fully-used sectors, float4-aligned)
//   2) transpose lines [48][512] -> [512][48]
//   3) sampling kernel: 16 lanes per point (12 active float4 lanes), bilinear
//      combine in registers, stage vm[48] in smem, then matvec with lane==output
//      and all 48 proj weights held in registers (loaded once per warp).

#define RES   512
#define RANK  48
#define OUT_C 32

__device__ float g_planes[3ull * RES * RES * RANK];   // ~151 MB transposed planes
__device__ float g_lines[3 * RES * RANK];             // transposed lines

// ---------------------------------------------------------------------------
// Transpose planes: in [R][512][512] -> g_planes [p][y][x][R]
// grid (4, 512, 3), block 256. Each block: one y row, 128 x values, all 48 r.
// ---------------------------------------------------------------------------
__global__ void transpose_planes(const float* __restrict__ pxy,
                                 const float* __restrict__ pxz,
                                 const float* __restrict__ pyz) {
    __shared__ float s[128 * 49];   // pad 49 -> conflict-free strided stores
    const int p  = blockIdx.z;
    const int y  = blockIdx.y;
    const int xb = blockIdx.x * 128;
    const float* in = (p == 0) ? pxy : (p == 1) ? pxz : pyz;

    // Load: coalesced along x for each channel r.
    for (int i = threadIdx.x; i < RANK * 128; i += blockDim.x) {
        int r  = i >> 7;
        int xl = i & 127;
        s[xl * 49 + r] = in[(size_t)r * (RES * RES) + (size_t)y * RES + xb + xl];
    }
    __syncthreads();

    // Store: fully coalesced, x-major [x][r].
    float* outp = g_planes + (size_t)p * (RES * RES * RANK)
                           + ((size_t)y * RES + xb) * RANK;
    for (int i = threadIdx.x; i < RANK * 128; i += blockDim.x) {
        int xl = i / RANK;
        int r  = i - xl * RANK;
        outp[i] = s[xl * 49 + r];
    }
}

// ---------------------------------------------------------------------------
// Transpose lines: in [R][512] -> g_lines [l][z][R]
// ---------------------------------------------------------------------------
__global__ void transpose_lines(const float* __restrict__ lz,
                                const float* __restrict__ ly,
                                const float* __restrict__ lx) {
    int i = blockIdx.x * blockDim.x + threadIdx.x;
    const int total = 3 * RES * RANK;
    if (i < total) {
        int p   = i / (RES * RANK);
        int rem = i - p * (RES * RANK);
        int z   = rem / RANK;
        int r   = rem - z * RANK;
        const float* in = (p == 0) ? lz : (p == 1) ? ly : lx;
        g_lines[i] = in[r * RES + z];
    }
}

// ---------------------------------------------------------------------------
// Main kernel. 256 threads = 8 warps; each warp handles 2 points per
// iteration (one per half-warp) in a grid-stride loop.
// ---------------------------------------------------------------------------
__global__ void __launch_bounds__(256)
geo_main(const float* __restrict__ coords,
         const float* __restrict__ projw,
         const float* __restrict__ projb,
         float* __restrict__ out, int npts) {
    __shared__ float s_vm[8][2][RANK];   // per warp, per half-warp point

    const int tid   = threadIdx.x;
    const int warp  = tid >> 5;
    const int lane  = tid & 31;
    const int half  = lane >> 4;     // which point of the warp's pair
    const int t     = lane & 15;     // sub-lane within half-warp

    // Per-lane output channel + its 48 weights in registers (loaded once).
    const int o = lane;              // 32 lanes == 32 outputs
    float4 wreg[12];
    #pragma unroll
    for (int c4 = 0; c4 < 12; c4++)
        wreg[c4] = reinterpret_cast<const float4*>(projw + o * RANK)[c4];
    const float bo = projb[o];

    const int warp_global = blockIdx.x * (blockDim.x >> 5) + warp;
    const int warp_count  = gridDim.x * (blockDim.x >> 5);

    for (int pb = warp_global * 2; pb < npts; pb += warp_count * 2) {
        const int p  = pb + half;
        const int pl = (p < npts) ? p : (npts - 1);   // clamp, guard store only

        const float cx = coords[3 * pl + 0] * 2.0f - 1.0f;
        const float cy = coords[3 * pl + 1] * 2.0f - 1.0f;
        const float cz = coords[3 * pl + 2] * 2.0f - 1.0f;

        float4 acc = make_float4(0.f, 0.f, 0.f, 0.f);

        #pragma unroll
        for (int q = 0; q < 3; q++) {
            // plane q sampled at (gx, gy); line q sampled at gl
            const float gx = (q == 2) ? cy : cx;
            const float gy = (q == 0) ? cy : cz;
            const float gl = (q == 0) ? cz : ((q == 1) ? cy : cx);

            float px = (gx + 1.0f) * 0.5f * 511.0f;
            float py = (gy + 1.0f) * 0.5f * 511.0f;
            px = fminf(fmaxf(px, 0.0f), 511.0f);
            py = fminf(fmaxf(py, 0.0f), 511.0f);
            const int   x0 = (int)floorf(px);
            const int   y0 = (int)floorf(py);
            const int   x1 = min(x0 + 1, 511);
            const int   y1 = min(y0 + 1, 511);
            const float wx = px - (float)x0;
            const float wy = py - (float)y0;

            const float* gp = g_planes + (size_t)q * (RES * RES * RANK);
            const float4* r00 = reinterpret_cast<const float4*>(gp + ((size_t)(y0 * RES) + x0) * RANK);
            const float4* r01 = reinterpret_cast<const float4*>(gp + ((size_t)(y0 * RES) + x1) * RANK);
            const float4* r10 = reinterpret_cast<const float4*>(gp + ((size_t)(y1 * RES) + x0) * RANK);
            const float4* r11 = reinterpret_cast<const float4*>(gp + ((size_t)(y1 * RES) + x1) * RANK);

            float pz = (gl + 1.0f) * 0.5f * 511.0f;
            pz = fminf(fmaxf(pz, 0.0f), 511.0f);
            const int   z0 = (int)floorf(pz);
            const int   z1 = min(z0 + 1, 511);
            const float wz = pz - (float)z0;
            const float4* l0 = reinterpret_cast<const float4*>(g_lines + (q * RES + z0) * RANK);
            const float4* l1 = reinterpret_cast<const float4*>(g_lines + (q * RES + z1) * RANK);

            if (t < 12) {
                const float w00 = (1.0f - wy) * (1.0f - wx);
                const float w01 = (1.0f - wy) * wx;
                const float w10 = wy * (1.0f - wx);
                const float w11 = wy * wx;

                const float4 v00 = __ldg(r00 + t);
                const float4 v01 = __ldg(r01 + t);
                const float4 v10 = __ldg(r10 + t);
                const float4 v11 = __ldg(r11 + t);

                float4 pv;
                pv.x = v00.x * w00 + v01.x * w01 + v10.x * w10 + v11.x * w11;
                pv.y = v00.y * w00 + v01.y * w01 + v10.y * w10 + v11.y * w11;
                pv.z = v00.z * w00 + v01.z * w01 + v10.z * w10 + v11.z * w11;
                pv.w = v00.w * w00 + v01.w * w01 + v10.w * w10 + v11.w * w11;

                const float4 a0 = __ldg(l0 + t);
                const float4 a1 = __ldg(l1 + t);
                float4 lv;
                lv.x = a0.x * (1.0f - wz) + a1.x * wz;
                lv.y = a0.y * (1.0f - wz) + a1.y * wz;
                lv.z = a0.z * (1.0f - wz) + a1.z * wz;
                lv.w = a0.w * (1.0f - wz) + a1.w * wz;

                acc.x += pv.x * lv.x;
                acc.y += pv.y * lv.y;
                acc.z += pv.z * lv.z;
                acc.w += pv.w * lv.w;
            }
        }

        // Stage vm[48] for this warp's two points.
        if (t < 12)
            reinterpret_cast<float4*>(s_vm[warp][half])[t] = acc;
        __syncwarp();

        // Matvec: each lane owns one output channel; weights are in registers.
        #pragma unroll
        for (int h = 0; h < 2; h++) {
            const int pp = pb + h;           // uniform across warp
            if (pp >= npts) break;
            const float4* sv = reinterpret_cast<const float4*>(s_vm[warp][h]);
            float s = 0.0f;
            #pragma unroll
            for (int c4 = 0; c4 < 12; c4++) {
                const float4 v = sv[c4];     // broadcast LDS
                const float4 w = wreg[c4];
                s += v.x * w.x + v.y * w.y + v.z * w.z + v.w * w.w;
            }
            out[(size_t)pp * OUT_C + o] = s + bo;
        }
        __syncwarp();
    }
}

// ---------------------------------------------------------------------------
extern "C" void kernel_launch(void* const* d_in, const int* in_sizes, int n_in,
                              void* d_out, int out_size) {
    const float* coords = (const float*)d_in[0];
    const float* pxy    = (const float*)d_in[1];
    const float* pxz    = (const float*)d_in[2];
    const float* pyz    = (const float*)d_in[3];
    const float* lz     = (const float*)d_in[4];
    const float* ly     = (const float*)d_in[5];
    const float* lx     = (const float*)d_in[6];
    const float* pw     = (const float*)d_in[7];
    const float* pbias  = (const float*)d_in[8];
    float* outp = (float*)d_out;
    const int npts = in_sizes[0] / 3;

    dim3 tgrid(4, RES, 3);
    transpose_planes<<<tgrid, 256>>>(pxy, pxz, pyz);
    transpose_lines<<<(3 * RES * RANK + 255) / 256, 256>>>(lz, ly, lx);
    geo_main<<<1184, 256>>>(coords, pw, pbias, outp, npts);
}

// round 2
// speedup vs baseline: 1.5189x; 1.5189x over previous
#include <cuda_runtime.h>
#include <cuda_fp16.h>
#include <cuda_bf16.h>
#include <cstdint>

// GeoEncoder: tri-plane + tri-line sampling with 48->32 projection.
// v2: fp16 grids with 128B-padded texel records (one L1 line per corner),
//     4 points per warp (8 lanes/point, 6 active), fp32 math everywhere else.

#define RES   512
#define RANK  48
#define PADC  64          // padded channel count (fp16) -> 128B per texel
#define OUT_C 32

__device__ __half g_planes_h[3ull * RES * RES * PADC];  // ~100 MB
__device__ __half g_lines_h[3 * RES * RANK];            // 144 KB

// ---------------------------------------------------------------------------
// Transpose+convert planes: [R][512][512] f32 -> [p][y][x][64] fp16 (pad=0)
// grid (4, 512, 3), block 256: one y row, 128 x values, all 48 channels.
// ---------------------------------------------------------------------------
__global__ void transpose_planes_h(const float* __restrict__ pxy,
                                   const float* __restrict__ pxz,
                                   const float* __restrict__ pyz) {
    __shared__ float s[128 * 49];
    const int p  = blockIdx.z;
    const int y  = blockIdx.y;
    const int xb = blockIdx.x * 128;
    const float* in = (p == 0) ? pxy : (p == 1) ? pxz : pyz;

    for (int i = threadIdx.x; i < RANK * 128; i += blockDim.x) {
        int r  = i >> 7;
        int xl = i & 127;
        s[xl * 49 + r] = in[(size_t)r * (RES * RES) + (size_t)y * RES + xb + xl];
    }
    __syncthreads();

    __half2* outp = reinterpret_cast<__half2*>(
        g_planes_h + ((size_t)p * (RES * RES) + (size_t)y * RES + xb) * PADC);
    for (int i = threadIdx.x; i < 128 * (PADC / 2); i += blockDim.x) {
        int xl = i >> 5;          // PADC/2 = 32 half2 per texel
        int c2 = i & 31;
        int c  = c2 * 2;
        float a = (c     < RANK) ? s[xl * 49 + c]     : 0.0f;
        float b = (c + 1 < RANK) ? s[xl * 49 + c + 1] : 0.0f;
        outp[i] = __floats2half2_rn(a, b);
    }
}

// ---------------------------------------------------------------------------
// Transpose+convert lines: [R][512] f32 -> [l][z][48] fp16
// ---------------------------------------------------------------------------
__global__ void transpose_lines_h(const float* __restrict__ lz,
                                  const float* __restrict__ ly,
                                  const float* __restrict__ lx) {
    int i = blockIdx.x * blockDim.x + threadIdx.x;
    const int total = 3 * RES * RANK;
    if (i < total) {
        int p   = i / (RES * RANK);
        int rem = i - p * (RES * RANK);
        int z   = rem / RANK;
        int r   = rem - z * RANK;
        const float* in = (p == 0) ? lz : (p == 1) ? ly : lx;
        g_lines_h[i] = __float2half(in[r * RES + z]);
    }
}

// ---------------------------------------------------------------------------
// Main kernel. Warp = 4 points; 8 lanes per point, lanes t<6 carry data
// (6 lanes x 8 fp16 = 48 channels). vm staged in smem; matvec with lane==output
// and all 48 proj weights in registers.
// ---------------------------------------------------------------------------
__global__ void __launch_bounds__(256)
geo_main(const float* __restrict__ coords,
         const float* __restrict__ projw,
         const float* __restrict__ projb,
         float* __restrict__ out, int npts) {
    __shared__ float s_vm[8][4][RANK];    // per warp, per point

    const int tid  = threadIdx.x;
    const int warp = tid >> 5;
    const int lane = tid & 31;
    const int sp   = lane >> 3;     // which of the warp's 4 points
    const int t    = lane & 7;      // sub-lane within point group

    // Per-lane output channel + its 48 weights in registers (one-time load).
    const int o = lane;
    float wreg[RANK];
    #pragma unroll
    for (int c = 0; c < RANK; c++) wreg[c] = projw[o * RANK + c];
    const float bo = projb[o];

    const int warp_global = blockIdx.x * (blockDim.x >> 5) + warp;
    const int warp_count  = gridDim.x * (blockDim.x >> 5);

    for (int pb = warp_global * 4; pb < npts; pb += warp_count * 4) {
        const int p  = pb + sp;
        const int pl = (p < npts) ? p : (npts - 1);

        const float cx = coords[3 * pl + 0] * 2.0f - 1.0f;
        const float cy = coords[3 * pl + 1] * 2.0f - 1.0f;
        const float cz = coords[3 * pl + 2] * 2.0f - 1.0f;

        // Accumulator: 8 channels per lane, as 4 float2.
        float2 acc0 = make_float2(0.f, 0.f), acc1 = acc0, acc2 = acc0, acc3 = acc0;

        #pragma unroll
        for (int q = 0; q < 3; q++) {
            const float gx = (q == 2) ? cy : cx;
            const float gy = (q == 0) ? cy : cz;
            const float gl = (q == 0) ? cz : ((q == 1) ? cy : cx);

            float px = fminf(fmaxf((gx + 1.0f) * 0.5f * 511.0f, 0.0f), 511.0f);
            float py = fminf(fmaxf((gy + 1.0f) * 0.5f * 511.0f, 0.0f), 511.0f);
            float pz = fminf(fmaxf((gl + 1.0f) * 0.5f * 511.0f, 0.0f), 511.0f);
            const int x0 = (int)floorf(px), y0 = (int)floorf(py), z0 = (int)floorf(pz);
            const int x1 = min(x0 + 1, 511), y1 = min(y0 + 1, 511), z1 = min(z0 + 1, 511);
            const float wx = px - (float)x0;
            const float wy = py - (float)y0;
            const float wz = pz - (float)z0;

            if (t < 6) {
                const __half* gp = g_planes_h + (size_t)q * (RES * RES * PADC);
                const uint4* r00 = reinterpret_cast<const uint4*>(gp + ((size_t)(y0 * RES) + x0) * PADC) + t;
                const uint4* r01 = reinterpret_cast<const uint4*>(gp + ((size_t)(y0 * RES) + x1) * PADC) + t;
                const uint4* r10 = reinterpret_cast<const uint4*>(gp + ((size_t)(y1 * RES) + x0) * PADC) + t;
                const uint4* r11 = reinterpret_cast<const uint4*>(gp + ((size_t)(y1 * RES) + x1) * PADC) + t;
                const uint4* l0  = reinterpret_cast<const uint4*>(g_lines_h + (q * RES + z0) * RANK) + t;
                const uint4* l1  = reinterpret_cast<const uint4*>(g_lines_h + (q * RES + z1) * RANK) + t;

                const uint4 u00 = __ldg(r00), u01 = __ldg(r01);
                const uint4 u10 = __ldg(r10), u11 = __ldg(r11);
                const uint4 a0  = __ldg(l0),  a1  = __ldg(l1);

                const float w00 = (1.0f - wy) * (1.0f - wx);
                const float w01 = (1.0f - wy) * wx;
                const float w10 = wy * (1.0f - wx);
                const float w11 = wy * wx;
                const float lz0 = 1.0f - wz;

                #pragma unroll
                for (int k = 0; k < 4; k++) {
                    const unsigned h00 = (&u00.x)[k], h01 = (&u01.x)[k];
                    const unsigned h10 = (&u10.x)[k], h11 = (&u11.x)[k];
                    const unsigned hl0 = (&a0.x)[k],  hl1 = (&a1.x)[k];
                    const float2 f00 = __half22float2(*reinterpret_cast<const __half2*>(&h00));
                    const float2 f01 = __half22float2(*reinterpret_cast<const __half2*>(&h01));
                    const float2 f10 = __half22float2(*reinterpret_cast<const __half2*>(&h10));
                    const float2 f11 = __half22float2(*reinterpret_cast<const __half2*>(&h11));
                    const float2 g0  = __half22float2(*reinterpret_cast<const __half2*>(&hl0));
                    const float2 g1  = __half22float2(*reinterpret_cast<const __half2*>(&hl1));

                    float pvx = f00.x * w00 + f01.x * w01 + f10.x * w10 + f11.x * w11;
                    float pvy = f00.y * w00 + f01.y * w01 + f10.y * w10 + f11.y * w11;
                    float lvx = g0.x * lz0 + g1.x * wz;
                    float lvy = g0.y * lz0 + g1.y * wz;

                    float2* accp = (k == 0) ? &acc0 : (k == 1) ? &acc1 : (k == 2) ? &acc2 : &acc3;
                    accp->x += pvx * lvx;
                    accp->y += pvy * lvy;
                }
            }
        }

        // Stage vm[48] for this warp's four points (channels [8t, 8t+8) per lane).
        if (t < 6) {
            float4* dst = reinterpret_cast<float4*>(&s_vm[warp][sp][t * 8]);
            dst[0] = make_float4(acc0.x, acc0.y, acc1.x, acc1.y);
            dst[1] = make_float4(acc2.x, acc2.y, acc3.x, acc3.y);
        }
        __syncwarp();

        // Matvec: each lane owns one output channel; weights in registers.
        #pragma unroll
        for (int h = 0; h < 4; h++) {
            const int pp = pb + h;                // uniform across warp
            if (pp >= npts) break;
            const float4* sv = reinterpret_cast<const float4*>(s_vm[warp][h]);
            float s = bo;
            #pragma unroll
            for (int c4 = 0; c4 < 12; c4++) {
                const float4 v = sv[c4];          // broadcast LDS
                s += v.x * wreg[c4 * 4 + 0] + v.y * wreg[c4 * 4 + 1]
                   + v.z * wreg[c4 * 4 + 2] + v.w * wreg[c4 * 4 + 3];
            }
            out[(size_t)pp * OUT_C + o] = s;
        }
        __syncwarp();
    }
}

// ---------------------------------------------------------------------------
extern "C" void kernel_launch(void* const* d_in, const int* in_sizes, int n_in,
                              void* d_out, int out_size) {
    const float* coords = (const float*)d_in[0];
    const float* pxy    = (const float*)d_in[1];
    const float* pxz    = (const float*)d_in[2];
    const float* pyz    = (const float*)d_in[3];
    const float* lz     = (const float*)d_in[4];
    const float* ly     = (const float*)d_in[5];
    const float* lx     = (const float*)d_in[6];
    const float* pw     = (const float*)d_in[7];
    const float* pbias  = (const float*)d_in[8];
    float* outp = (float*)d_out;
    const int npts = in_sizes[0] / 3;

    dim3 tgrid(4, RES, 3);
    transpose_planes_h<<<tgrid, 256>>>(pxy, pxz, pyz);
    transpose_lines_h<<<(3 * RES * RANK + 255) / 256, 256>>>(lz, ly, lx);
    geo_main<<<1184, 256>>>(coords, pw, pbias, outp, npts);
}

// round 3
// speedup vs baseline: 2.2573x; 1.4862x over previous
#include <cuda_runtime.h>
#include <cuda_fp16.h>
#include <cuda_bf16.h>
#include <cstdint>

// GeoEncoder v3: fp16 grids (128B texel records), packed f32x2 FMA math,
// streaming hints to keep planes L2-resident, 2 launches per call.

#define RES   512
#define RANK  48
#define PADC  64
#define OUT_C 32

typedef unsigned long long u64;

__device__ __half g_planes_h[3ull * RES * RES * PADC];  // ~100 MB
__device__ __half g_lines_h[3 * RES * RANK];            // 144 KB

// ---- packed f32x2 helpers (FFMA2 path, PTX-only) --------------------------
__device__ __forceinline__ u64 pk2(float lo, float hi) {
    u64 r; asm("mov.b64 %0,{%1,%2};" : "=l"(r) : "f"(lo), "f"(hi)); return r;
}
__device__ __forceinline__ float2 upk2(u64 a) {
    float2 f; asm("mov.b64 {%0,%1},%2;" : "=f"(f.x), "=f"(f.y) : "l"(a)); return f;
}
__device__ __forceinline__ u64 f2fma(u64 a, u64 b, u64 c) {
    u64 d; asm("fma.rn.f32x2 %0,%1,%2,%3;" : "=l"(d) : "l"(a), "l"(b), "l"(c)); return d;
}
__device__ __forceinline__ u64 f2mul(u64 a, u64 b) {
    u64 d; asm("mul.rn.f32x2 %0,%1,%2;" : "=l"(d) : "l"(a), "l"(b)); return d;
}
__device__ __forceinline__ u64 h2f2(unsigned h) {
    float2 f = __half22float2(*reinterpret_cast<const __half2*>(&h));
    return pk2(f.x, f.y);
}

// ---------------------------------------------------------------------------
// Prep: transpose+convert planes [R][512][512] f32 -> [p][y][x][64] fp16,
// and lines [R][512] -> [l][z][48] fp16. grid (4,512,4); z==3 does lines.
// ---------------------------------------------------------------------------
__global__ void prep_grids(const float* __restrict__ pxy,
                           const float* __restrict__ pxz,
                           const float* __restrict__ pyz,
                           const float* __restrict__ lz,
                           const float* __restrict__ ly,
                           const float* __restrict__ lx) {
    if (blockIdx.z == 3) {
        const int total = 3 * RES * RANK;
        int i = ((blockIdx.y * gridDim.x + blockIdx.x) * blockDim.x) + threadIdx.x;
        if (i < total) {
            int p   = i / (RES * RANK);
            int rem = i - p * (RES * RANK);
            int z   = rem / RANK;
            int r   = rem - z * RANK;
            const float* in = (p == 0) ? lz : (p == 1) ? ly : lx;
            g_lines_h[i] = __float2half(in[r * RES + z]);
        }
        return;
    }
    __shared__ float s[128 * 49];
    const int p  = blockIdx.z;
    const int y  = blockIdx.y;
    const int xb = blockIdx.x * 128;
    const float* in = (p == 0) ? pxy : (p == 1) ? pxz : pyz;

    for (int i = threadIdx.x; i < RANK * 128; i += blockDim.x) {
        int r  = i >> 7;
        int xl = i & 127;
        s[xl * 49 + r] = in[(size_t)r * (RES * RES) + (size_t)y * RES + xb + xl];
    }
    __syncthreads();

    __half2* outp = reinterpret_cast<__half2*>(
        g_planes_h + ((size_t)p * (RES * RES) + (size_t)y * RES + xb) * PADC);
    for (int i = threadIdx.x; i < 128 * (PADC / 2); i += blockDim.x) {
        int xl = i >> 5;
        int c  = (i & 31) * 2;
        float a = (c     < RANK) ? s[xl * 49 + c]     : 0.0f;
        float b = (c + 1 < RANK) ? s[xl * 49 + c + 1] : 0.0f;
        outp[i] = __floats2half2_rn(a, b);
    }
}

// ---------------------------------------------------------------------------
// Main kernel. Warp = 4 points; 8 lanes/point, t<6 carry 8 fp16 channels.
// All interp + matvec math in packed f32x2 FMA. Output via streaming store.
// ---------------------------------------------------------------------------
__global__ void __launch_bounds__(256)
geo_main(const float* __restrict__ coords,
         const float* __restrict__ projw,
         const float* __restrict__ projb,
         float* __restrict__ out, int npts) {
    __shared__ u64 s_vm[8][4][24];   // per warp, per point: 24 packed ch-pairs

    const int tid  = threadIdx.x;
    const int warp = tid >> 5;
    const int lane = tid & 31;
    const int sp   = lane >> 3;
    const int t    = lane & 7;

    // Lane-owned output channel: 24 packed weight pairs in registers.
    const int o = lane;
    u64 wp[24];
    #pragma unroll
    for (int c2 = 0; c2 < 24; c2++)
        wp[c2] = pk2(projw[o * RANK + 2 * c2], projw[o * RANK + 2 * c2 + 1]);
    const float bo = projb[o];

    const int warp_global = blockIdx.x * (blockDim.x >> 5) + warp;
    const int warp_count  = gridDim.x * (blockDim.x >> 5);
    const int maxcidx     = npts * 3 - 1;

    for (int pb = warp_global * 4; pb < npts; pb += warp_count * 4) {
        // Coalesced coord fetch: 12 lanes load, everyone shuffles.
        float cv = 0.0f;
        if (lane < 12) cv = __ldcs(coords + min(3 * pb + lane, maxcidx));
        const float cx = __shfl_sync(0xffffffffu, cv, sp * 3 + 0) * 2.0f - 1.0f;
        const float cy = __shfl_sync(0xffffffffu, cv, sp * 3 + 1) * 2.0f - 1.0f;
        const float cz = __shfl_sync(0xffffffffu, cv, sp * 3 + 2) * 2.0f - 1.0f;

        u64 acc[4];
        #pragma unroll
        for (int k = 0; k < 4; k++) acc[k] = pk2(0.0f, 0.0f);

        #pragma unroll
        for (int q = 0; q < 3; q++) {
            const float gx = (q == 2) ? cy : cx;
            const float gy = (q == 0) ? cy : cz;
            const float gl = (q == 0) ? cz : ((q == 1) ? cy : cx);

            float px = fminf(fmaxf((gx + 1.0f) * 0.5f * 511.0f, 0.0f), 511.0f);
            float py = fminf(fmaxf((gy + 1.0f) * 0.5f * 511.0f, 0.0f), 511.0f);
            float pz = fminf(fmaxf((gl + 1.0f) * 0.5f * 511.0f, 0.0f), 511.0f);
            const int x0 = (int)floorf(px), y0 = (int)floorf(py), z0 = (int)floorf(pz);
            const int x1 = min(x0 + 1, 511), y1 = min(y0 + 1, 511), z1 = min(z0 + 1, 511);
            const float wx = px - (float)x0;
            const float wy = py - (float)y0;
            const float wz = pz - (float)z0;

            const float w00 = (1.0f - wy) * (1.0f - wx);
            const float w01 = (1.0f - wy) * wx;
            const float w10 = wy * (1.0f - wx);
            const float w11 = wy * wx;
            const u64 w00p = pk2(w00, w00), w01p = pk2(w01, w01);
            const u64 w10p = pk2(w10, w10), w11p = pk2(w11, w11);
            const u64 lz0p = pk2(1.0f - wz, 1.0f - wz), wzp = pk2(wz, wz);

            if (t < 6) {
                const __half* gp = g_planes_h + (size_t)q * (RES * RES * PADC);
                const uint4 u00 = __ldg(reinterpret_cast<const uint4*>(gp + ((size_t)(y0 * RES) + x0) * PADC) + t);
                const uint4 u01 = __ldg(reinterpret_cast<const uint4*>(gp + ((size_t)(y0 * RES) + x1) * PADC) + t);
                const uint4 u10 = __ldg(reinterpret_cast<const uint4*>(gp + ((size_t)(y1 * RES) + x0) * PADC) + t);
                const uint4 u11 = __ldg(reinterpret_cast<const uint4*>(gp + ((size_t)(y1 * RES) + x1) * PADC) + t);
                const uint4 a0  = __ldg(reinterpret_cast<const uint4*>(g_lines_h + (q * RES + z0) * RANK) + t);
                const uint4 a1  = __ldg(reinterpret_cast<const uint4*>(g_lines_h + (q * RES + z1) * RANK) + t);

                #pragma unroll
                for (int k = 0; k < 4; k++) {
                    const u64 f00 = h2f2((&u00.x)[k]);
                    const u64 f01 = h2f2((&u01.x)[k]);
                    const u64 f10 = h2f2((&u10.x)[k]);
                    const u64 f11 = h2f2((&u11.x)[k]);
                    const u64 g0  = h2f2((&a0.x)[k]);
                    const u64 g1  = h2f2((&a1.x)[k]);

                    const u64 pv = f2fma(f00, w00p,
                                    f2fma(f01, w01p,
                                     f2fma(f10, w10p, f2mul(f11, w11p))));
                    const u64 lv = f2fma(g0, lz0p, f2mul(g1, wzp));
                    acc[k] = f2fma(pv, lv, acc[k]);
                }
            }
        }

        // Stage vm (packed pairs) for this warp's 4 points.
        if (t < 6) {
            #pragma unroll
            for (int k = 0; k < 4; k++)
                s_vm[warp][sp][t * 4 + k] = acc[k];
        }
        __syncwarp();

        // Matvec: lane == output channel, packed weights in registers.
        #pragma unroll
        for (int h = 0; h < 4; h++) {
            const int pp = pb + h;             // uniform across warp
            if (pp >= npts) break;
            const u64* sv = s_vm[warp][h];
            u64 s2 = pk2(0.0f, 0.0f);
            #pragma unroll
            for (int c2 = 0; c2 < 24; c2++)
                s2 = f2fma(sv[c2], wp[c2], s2);
            const float2 f = upk2(s2);
            __stcs(out + (size_t)pp * OUT_C + o, f.x + f.y + bo);
        }
        __syncwarp();
    }
}

// ---------------------------------------------------------------------------
extern "C" void kernel_launch(void* const* d_in, const int* in_sizes, int n_in,
                              void* d_out, int out_size) {
    const float* coords = (const float*)d_in[0];
    const float* pxy    = (const float*)d_in[1];
    const float* pxz    = (const float*)d_in[2];
    const float* pyz    = (const float*)d_in[3];
    const float* lz     = (const float*)d_in[4];
    const float* ly     = (const float*)d_in[5];
    const float* lx     = (const float*)d_in[6];
    const float* pw     = (const float*)d_in[7];
    const float* pbias  = (const float*)d_in[8];
    float* outp = (float*)d_out;
    const int npts = in_sizes[0] / 3;

    dim3 tgrid(4, RES, 4);
    prep_grids<<<tgrid, 256>>>(pxy, pxz, pyz, lz, ly, lx);
    geo_main<<<1184, 256>>>(coords, pw, pbias, outp, npts);
}

// round 5
// speedup vs baseline: 2.6828x; 1.1885x over previous
#include <cuda_runtime.h>
#include <cuda_fp16.h>
#include <cuda_bf16.h>
#include <cstdint>

// GeoEncoder v4: fp16 grids (128B texel records, 64-ch padded), packed f32x2
// math, branchless all-8-lane sampling, occupancy forced to 3 CTAs/SM.

#define RES   512
#define RANK  48
#define PADC  64          // padded channels -> 128B per texel record
#define OUT_C 32

typedef unsigned long long u64;

__device__ __half g_planes_h[3ull * RES * RES * PADC];  // ~100 MB
__device__ __half g_lines_h[3 * RES * PADC];            // 192 KB (64-padded)

// ---- packed f32x2 helpers -------------------------------------------------
__device__ __forceinline__ u64 pk2(float lo, float hi) {
    u64 r; asm("mov.b64 %0,{%1,%2};" : "=l"(r) : "f"(lo), "f"(hi)); return r;
}
__device__ __forceinline__ float2 upk2(u64 a) {
    float2 f; asm("mov.b64 {%0,%1},%2;" : "=f"(f.x), "=f"(f.y) : "l"(a)); return f;
}
__device__ __forceinline__ u64 f2fma(u64 a, u64 b, u64 c) {
    u64 d; asm("fma.rn.f32x2 %0,%1,%2,%3;" : "=l"(d) : "l"(a), "l"(b), "l"(c)); return d;
}
__device__ __forceinline__ u64 f2mul(u64 a, u64 b) {
    u64 d; asm("mul.rn.f32x2 %0,%1,%2;" : "=l"(d) : "l"(a), "l"(b)); return d;
}
__device__ __forceinline__ u64 h2f2(unsigned h) {
    float2 f = __half22float2(*reinterpret_cast<const __half2*>(&h));
    return pk2(f.x, f.y);
}

// ---------------------------------------------------------------------------
// Prep: planes [R][512][512] f32 -> [p][y][x][64] fp16 (pad 0);
//       lines  [R][512]       -> [l][z][64] fp16 (pad 0).  z==3 does lines.
// ---------------------------------------------------------------------------
__global__ void prep_grids(const float* __restrict__ pxy,
                           const float* __restrict__ pxz,
                           const float* __restrict__ pyz,
                           const float* __restrict__ lz,
                           const float* __restrict__ ly,
                           const float* __restrict__ lx) {
    if (blockIdx.z == 3) {
        const int total = 3 * RES * PADC;
        int i = ((blockIdx.y * gridDim.x + blockIdx.x) * blockDim.x) + threadIdx.x;
        if (i < total) {
            int p   = i / (RES * PADC);
            int rem = i - p * (RES * PADC);
            int z   = rem / PADC;
            int r   = rem - z * PADC;
            const float* in = (p == 0) ? lz : (p == 1) ? ly : lx;
            g_lines_h[i] = (r < RANK) ? __float2half(in[r * RES + z]) : __half(0.0f);
        }
        return;
    }
    __shared__ float s[128 * 49];
    const int p  = blockIdx.z;
    const int y  = blockIdx.y;
    const int xb = blockIdx.x * 128;
    const float* in = (p == 0) ? pxy : (p == 1) ? pxz : pyz;

    for (int i = threadIdx.x; i < RANK * 128; i += blockDim.x) {
        int r  = i >> 7;
        int xl = i & 127;
        s[xl * 49 + r] = in[(size_t)r * (RES * RES) + (size_t)y * RES + xb + xl];
    }
    __syncthreads();

    __half2* outp = reinterpret_cast<__half2*>(
        g_planes_h + ((size_t)p * (RES * RES) + (size_t)y * RES + xb) * PADC);
    for (int i = threadIdx.x; i < 128 * (PADC / 2); i += blockDim.x) {
        int xl = i >> 5;
        int c  = (i & 31) * 2;
        float a = (c     < RANK) ? s[xl * 49 + c]     : 0.0f;
        float b = (c + 1 < RANK) ? s[xl * 49 + c + 1] : 0.0f;
        outp[i] = __floats2half2_rn(a, b);
    }
}

// ---------------------------------------------------------------------------
// Main kernel. Warp = 4 points; 8 lanes/point, each carries 8 channels
// (lanes 6,7 carry zero padding -> fully branchless). f32x2 FMA math.
// ---------------------------------------------------------------------------
__global__ void __launch_bounds__(256, 3)
geo_main(const float* __restrict__ coords,
         const float* __restrict__ projw,
         const float* __restrict__ projb,
         float* __restrict__ out, int npts) {
    __shared__ u64 s_vm[8][4][32];   // per warp, per point: 32 packed pairs

    const int tid  = threadIdx.x;
    const int warp = tid >> 5;
    const int lane = tid & 31;
    const int sp   = lane >> 3;
    const int t    = lane & 7;

    // Lane-owned output channel: 24 packed f32 weight pairs (precision-critical).
    const int o = lane;
    u64 wp[24];
    #pragma unroll
    for (int c2 = 0; c2 < 24; c2++)
        wp[c2] = pk2(projw[o * RANK + 2 * c2], projw[o * RANK + 2 * c2 + 1]);
    const float bo = projb[o];

    const int warp_global = blockIdx.x * (blockDim.x >> 5) + warp;
    const int warp_count  = gridDim.x * (blockDim.x >> 5);
    const int maxcidx     = npts * 3 - 1;

    for (int pb = warp_global * 4; pb < npts; pb += warp_count * 4) {
        // Coalesced coord fetch: 12 lanes load, everyone shuffles.
        float cv = 0.0f;
        if (lane < 12) cv = __ldcs(coords + min(3 * pb + lane, maxcidx));
        const float cx = __shfl_sync(0xffffffffu, cv, sp * 3 + 0) * 2.0f - 1.0f;
        const float cy = __shfl_sync(0xffffffffu, cv, sp * 3 + 1) * 2.0f - 1.0f;
        const float cz = __shfl_sync(0xffffffffu, cv, sp * 3 + 2) * 2.0f - 1.0f;

        u64 acc[4];
        #pragma unroll
        for (int k = 0; k < 4; k++) acc[k] = pk2(0.0f, 0.0f);

        #pragma unroll
        for (int q = 0; q < 3; q++) {
            const float gx = (q == 2) ? cy : cx;
            const float gy = (q == 0) ? cy : cz;
            const float gl = (q == 0) ? cz : ((q == 1) ? cy : cx);

            float px = fminf(fmaxf((gx + 1.0f) * 0.5f * 511.0f, 0.0f), 511.0f);
            float py = fminf(fmaxf((gy + 1.0f) * 0.5f * 511.0f, 0.0f), 511.0f);
            float pz = fminf(fmaxf((gl + 1.0f) * 0.5f * 511.0f, 0.0f), 511.0f);
            const int x0 = (int)floorf(px), y0 = (int)floorf(py), z0 = (int)floorf(pz);
            const int x1 = min(x0 + 1, 511), y1 = min(y0 + 1, 511), z1 = min(z0 + 1, 511);
            const float wx = px - (float)x0;
            const float wy = py - (float)y0;
            const float wz = pz - (float)z0;

            const float w00 = (1.0f - wy) * (1.0f - wx);
            const float w01 = (1.0f - wy) * wx;
            const float w10 = wy * (1.0f - wx);
            const float w11 = wy * wx;
            const u64 w00p = pk2(w00, w00), w01p = pk2(w01, w01);
            const u64 w10p = pk2(w10, w10), w11p = pk2(w11, w11);
            const u64 lz0p = pk2(1.0f - wz, 1.0f - wz), wzp = pk2(wz, wz);

            const __half* gp = g_planes_h + (size_t)q * (RES * RES * PADC);
            const uint4 u00 = __ldg(reinterpret_cast<const uint4*>(gp + ((size_t)(y0 * RES) + x0) * PADC) + t);
            const uint4 u01 = __ldg(reinterpret_cast<const uint4*>(gp + ((size_t)(y0 * RES) + x1) * PADC) + t);
            const uint4 u10 = __ldg(reinterpret_cast<const uint4*>(gp + ((size_t)(y1 * RES) + x0) * PADC) + t);
            const uint4 u11 = __ldg(reinterpret_cast<const uint4*>(gp + ((size_t)(y1 * RES) + x1) * PADC) + t);
            const uint4 a0  = __ldg(reinterpret_cast<const uint4*>(g_lines_h + (q * RES + z0) * PADC) + t);
            const uint4 a1  = __ldg(reinterpret_cast<const uint4*>(g_lines_h + (q * RES + z1) * PADC) + t);

            #pragma unroll
            for (int k = 0; k < 4; k++) {
                const u64 f00 = h2f2((&u00.x)[k]);
                const u64 f01 = h2f2((&u01.x)[k]);
                const u64 f10 = h2f2((&u10.x)[k]);
                const u64 f11 = h2f2((&u11.x)[k]);
                const u64 g0  = h2f2((&a0.x)[k]);
                const u64 g1  = h2f2((&a1.x)[k]);

                const u64 pv = f2fma(f00, w00p,
                                f2fma(f01, w01p,
                                 f2fma(f10, w10p, f2mul(f11, w11p))));
                const u64 lv = f2fma(g0, lz0p, f2mul(g1, wzp));
                acc[k] = f2fma(pv, lv, acc[k]);
            }
        }

        // Stage vm (packed pairs) for this warp's 4 points (pad lanes store 0).
        #pragma unroll
        for (int k = 0; k < 4; k++)
            s_vm[warp][sp][t * 4 + k] = acc[k];
        __syncwarp();

        // Matvec: lane == output channel, packed f32 weights in registers.
        #pragma unroll
        for (int h = 0; h < 4; h++) {
            const int pp = pb + h;             // uniform across warp
            if (pp >= npts) break;
            const u64* sv = s_vm[warp][h];
            u64 s2 = pk2(0.0f, 0.0f);
            #pragma unroll
            for (int c2 = 0; c2 < 24; c2++)
                s2 = f2fma(sv[c2], wp[c2], s2);
            const float2 f = upk2(s2);
            __stcs(out + (size_t)pp * OUT_C + o, f.x + f.y + bo);
        }
        __syncwarp();
    }
}

// ---------------------------------------------------------------------------
extern "C" void kernel_launch(void* const* d_in, const int* in_sizes, int n_in,
                              void* d_out, int out_size) {
    const float* coords = (const float*)d_in[0];
    const float* pxy    = (const float*)d_in[1];
    const float* pxz    = (const float*)d_in[2];
    const float* pyz    = (const float*)d_in[3];
    const float* lz     = (const float*)d_in[4];
    const float* ly     = (const float*)d_in[5];
    const float* lx     = (const float*)d_in[6];
    const float* pw     = (const float*)d_in[7];
    const float* pbias  = (const float*)d_in[8];
    float* outp = (float*)d_out;
    const int npts = in_sizes[0] / 3;

    dim3 tgrid(4, RES, 4);
    prep_grids<<<tgrid, 256>>>(pxy, pxz, pyz, lz, ly, lx);
    geo_main<<<444, 256>>>(coords, pw, pbias, outp, npts);
}

// round 7
// speedup vs baseline: 2.7949x; 1.0418x over previous
#include <cuda_runtime.h>
#include <cuda_fp16.h>
#include <cuda_bf16.h>
#include <cstdint>

// GeoEncoder v6: v5 (smem weights, 4 CTAs/SM) with the s_vm overflow fixed:
// each point slot is 32 pairs so pad lanes (t=6,7) write into dead space.

#define RES   512
#define RANK  48
#define PADC  64
#define OUT_C 32

typedef unsigned long long u64;

__device__ __half g_planes_h[3ull * RES * RES * PADC];  // ~100 MB
__device__ __half g_lines_h[3 * RES * PADC];            // 192 KB

// ---- packed f32x2 helpers -------------------------------------------------
__device__ __forceinline__ u64 pk2(float lo, float hi) {
    u64 r; asm("mov.b64 %0,{%1,%2};" : "=l"(r) : "f"(lo), "f"(hi)); return r;
}
__device__ __forceinline__ float2 upk2(u64 a) {
    float2 f; asm("mov.b64 {%0,%1},%2;" : "=f"(f.x), "=f"(f.y) : "l"(a)); return f;
}
__device__ __forceinline__ u64 f2fma(u64 a, u64 b, u64 c) {
    u64 d; asm("fma.rn.f32x2 %0,%1,%2,%3;" : "=l"(d) : "l"(a), "l"(b), "l"(c)); return d;
}
__device__ __forceinline__ u64 f2mul(u64 a, u64 b) {
    u64 d; asm("mul.rn.f32x2 %0,%1,%2;" : "=l"(d) : "l"(a), "l"(b)); return d;
}
__device__ __forceinline__ u64 h2f2(unsigned h) {
    float2 f = __half22float2(*reinterpret_cast<const __half2*>(&h));
    return pk2(f.x, f.y);
}
__device__ __forceinline__ u64 mkpair(unsigned lo, unsigned hi) {
    u64 r; asm("mov.b64 %0,{%1,%2};" : "=l"(r) : "r"(lo), "r"(hi)); return r;
}

// ---------------------------------------------------------------------------
// Prep: planes [R][512][512] f32 -> [p][y][x][64] fp16 (pad 0);
//       lines  [R][512]       -> [l][z][64] fp16 (pad 0).  z==3 does lines.
// ---------------------------------------------------------------------------
__global__ void prep_grids(const float* __restrict__ pxy,
                           const float* __restrict__ pxz,
                           const float* __restrict__ pyz,
                           const float* __restrict__ lz,
                           const float* __restrict__ ly,
                           const float* __restrict__ lx) {
    if (blockIdx.z == 3) {
        const int total = 3 * RES * PADC;
        int i = ((blockIdx.y * gridDim.x + blockIdx.x) * blockDim.x) + threadIdx.x;
        if (i < total) {
            int p   = i / (RES * PADC);
            int rem = i - p * (RES * PADC);
            int z   = rem / PADC;
            int r   = rem - z * PADC;
            const float* in = (p == 0) ? lz : (p == 1) ? ly : lx;
            g_lines_h[i] = (r < RANK) ? __float2half(in[r * RES + z]) : __half(0.0f);
        }
        return;
    }
    __shared__ float s[128 * 49];
    const int p  = blockIdx.z;
    const int y  = blockIdx.y;
    const int xb = blockIdx.x * 128;
    const float* in = (p == 0) ? pxy : (p == 1) ? pxz : pyz;

    for (int i = threadIdx.x; i < RANK * 128; i += blockDim.x) {
        int r  = i >> 7;
        int xl = i & 127;
        s[xl * 49 + r] = in[(size_t)r * (RES * RES) + (size_t)y * RES + xb + xl];
    }
    __syncthreads();

    __half2* outp = reinterpret_cast<__half2*>(
        g_planes_h + ((size_t)p * (RES * RES) + (size_t)y * RES + xb) * PADC);
    for (int i = threadIdx.x; i < 128 * (PADC / 2); i += blockDim.x) {
        int xl = i >> 5;
        int c  = (i & 31) * 2;
        float a = (c     < RANK) ? s[xl * 49 + c]     : 0.0f;
        float b = (c + 1 < RANK) ? s[xl * 49 + c + 1] : 0.0f;
        outp[i] = __floats2half2_rn(a, b);
    }
}

// ---------------------------------------------------------------------------
// Main kernel. Warp = 4 points; 8 lanes/point, each carries 8 channels.
// Weights live in smem s_w[c2][o] (packed f32 pairs), freeing registers.
// ---------------------------------------------------------------------------
__global__ void __launch_bounds__(256, 4)
geo_main(const float* __restrict__ coords,
         const float* __restrict__ projw,
         const float* __restrict__ projb,
         float* __restrict__ out, int npts) {
    __shared__ alignas(16) u64 s_vm[8][4][32];   // 32 pairs/point: t=6,7 pad area
    __shared__ u64 s_w[24][OUT_C];               // transposed packed weights

    const int tid  = threadIdx.x;
    const int warp = tid >> 5;
    const int lane = tid & 31;
    const int sp   = lane >> 3;
    const int t    = lane & 7;
    const int o    = lane;                        // output channel for matvec

    // Stage weights once per block (transposed, lane-contiguous).
    for (int i = tid; i < 24 * OUT_C; i += blockDim.x) {
        int c2 = i >> 5, oo = i & 31;
        s_w[c2][oo] = pk2(projw[oo * RANK + 2 * c2], projw[oo * RANK + 2 * c2 + 1]);
    }
    __syncthreads();
    const float bo = projb[o];

    const int warp_global = blockIdx.x * (blockDim.x >> 5) + warp;
    const int warp_count  = gridDim.x * (blockDim.x >> 5);
    const int maxcidx     = npts * 3 - 1;

    for (int pb = warp_global * 4; pb < npts; pb += warp_count * 4) {
        // Coalesced coord fetch: 12 lanes load, everyone shuffles.
        float cv = 0.0f;
        if (lane < 12) cv = __ldcs(coords + min(3 * pb + lane, maxcidx));
        const float cx = __shfl_sync(0xffffffffu, cv, sp * 3 + 0) * 2.0f - 1.0f;
        const float cy = __shfl_sync(0xffffffffu, cv, sp * 3 + 1) * 2.0f - 1.0f;
        const float cz = __shfl_sync(0xffffffffu, cv, sp * 3 + 2) * 2.0f - 1.0f;

        u64 acc[4];
        #pragma unroll
        for (int k = 0; k < 4; k++) acc[k] = pk2(0.0f, 0.0f);

        #pragma unroll
        for (int q = 0; q < 3; q++) {
            const float gx = (q == 2) ? cy : cx;
            const float gy = (q == 0) ? cy : cz;
            const float gl = (q == 0) ? cz : ((q == 1) ? cy : cx);

            float px = fminf(fmaxf((gx + 1.0f) * 0.5f * 511.0f, 0.0f), 511.0f);
            float py = fminf(fmaxf((gy + 1.0f) * 0.5f * 511.0f, 0.0f), 511.0f);
            float pz = fminf(fmaxf((gl + 1.0f) * 0.5f * 511.0f, 0.0f), 511.0f);
            const int x0 = (int)floorf(px), y0 = (int)floorf(py), z0 = (int)floorf(pz);
            const int x1 = min(x0 + 1, 511), y1 = min(y0 + 1, 511), z1 = min(z0 + 1, 511);
            const float wx = px - (float)x0;
            const float wy = py - (float)y0;
            const float wz = pz - (float)z0;

            const float w00 = (1.0f - wy) * (1.0f - wx);
            const float w01 = (1.0f - wy) * wx;
            const float w10 = wy * (1.0f - wx);
            const float w11 = wy * wx;
            const u64 w00p = pk2(w00, w00), w01p = pk2(w01, w01);
            const u64 w10p = pk2(w10, w10), w11p = pk2(w11, w11);
            const u64 lz0p = pk2(1.0f - wz, 1.0f - wz), wzp = pk2(wz, wz);

            const __half* gp = g_planes_h + (size_t)q * (RES * RES * PADC);
            const uint4 u00 = __ldg(reinterpret_cast<const uint4*>(gp + ((size_t)(y0 * RES) + x0) * PADC) + t);
            const uint4 u01 = __ldg(reinterpret_cast<const uint4*>(gp + ((size_t)(y0 * RES) + x1) * PADC) + t);
            const uint4 u10 = __ldg(reinterpret_cast<const uint4*>(gp + ((size_t)(y1 * RES) + x0) * PADC) + t);
            const uint4 u11 = __ldg(reinterpret_cast<const uint4*>(gp + ((size_t)(y1 * RES) + x1) * PADC) + t);
            const uint4 a0  = __ldg(reinterpret_cast<const uint4*>(g_lines_h + (q * RES + z0) * PADC) + t);
            const uint4 a1  = __ldg(reinterpret_cast<const uint4*>(g_lines_h + (q * RES + z1) * PADC) + t);

            #pragma unroll
            for (int k = 0; k < 4; k++) {
                const u64 f00 = h2f2((&u00.x)[k]);
                const u64 f01 = h2f2((&u01.x)[k]);
                const u64 f10 = h2f2((&u10.x)[k]);
                const u64 f11 = h2f2((&u11.x)[k]);
                const u64 g0  = h2f2((&a0.x)[k]);
                const u64 g1  = h2f2((&a1.x)[k]);

                const u64 pv = f2fma(f00, w00p,
                                f2fma(f01, w01p,
                                 f2fma(f10, w10p, f2mul(f11, w11p))));
                const u64 lv = f2fma(g0, lz0p, f2mul(g1, wzp));
                acc[k] = f2fma(pv, lv, acc[k]);
            }
        }

        // Stage vm via two STS.128 per lane (t=6,7 write zero pad, in-bounds).
        {
            const float2 a0 = upk2(acc[0]), a1 = upk2(acc[1]);
            const float2 a2 = upk2(acc[2]), a3 = upk2(acc[3]);
            float4* dst = reinterpret_cast<float4*>(&s_vm[warp][sp][t * 4]);
            dst[0] = make_float4(a0.x, a0.y, a1.x, a1.y);
            dst[1] = make_float4(a2.x, a2.y, a3.x, a3.y);
        }
        __syncwarp();

        // Matvec: lane == output channel; vm via LDS.128, weights via smem.
        #pragma unroll
        for (int h = 0; h < 4; h++) {
            const int pp = pb + h;               // uniform across warp
            if (pp >= npts) break;
            const uint4* sv = reinterpret_cast<const uint4*>(s_vm[warp][h]);
            u64 s2 = pk2(0.0f, 0.0f);
            #pragma unroll
            for (int c4 = 0; c4 < 12; c4++) {
                const uint4 v = sv[c4];          // broadcast LDS.128 = 2 pairs
                s2 = f2fma(mkpair(v.x, v.y), s_w[2 * c4 + 0][o], s2);
                s2 = f2fma(mkpair(v.z, v.w), s_w[2 * c4 + 1][o], s2);
            }
            const float2 f = upk2(s2);
            __stcs(out + (size_t)pp * OUT_C + o, f.x + f.y + bo);
        }
        __syncwarp();
    }
}

// ---------------------------------------------------------------------------
extern "C" void kernel_launch(void* const* d_in, const int* in_sizes, int n_in,
                              void* d_out, int out_size) {
    const float* coords = (const float*)d_in[0];
    const float* pxy    = (const float*)d_in[1];
    const float* pxz    = (const float*)d_in[2];
    const float* pyz    = (const float*)d_in[3];
    const float* lz     = (const float*)d_in[4];
    const float* ly     = (const float*)d_in[5];
    const float* lx     = (const float*)d_in[6];
    const float* pw     = (const float*)d_in[7];
    const float* pbias  = (const float*)d_in[8];
    float* outp = (float*)d_out;
    const int npts = in_sizes[0] / 3;

    dim3 tgrid(4, RES, 4);
    prep_grids<<<tgrid, 256>>>(pxy, pxz, pyz, lz, ly, lx);
    geo_main<<<592, 256>>>(coords, pw, pbias, outp, npts);
}